// round 13
// baseline (speedup 1.0000x reference)
#include <cuda_runtime.h>
#include <math.h>

#define NB 32
#define INT_MIN_V ((int)0x80000000)

// pmax slots (inputs): 0=x 1=w1 2=w2 3=w3 4=fw1 5=fw2
// maxbits slots (activations, atomic): 6=A1 7=A2 8=A3 9=F1
__device__ float g_pmax[6*32];
__device__ int   g_maxbits[10];

__device__ __align__(16) unsigned char g_qw2 [32*400];
__device__ __align__(16) unsigned char g_qw3 [64*800];
__device__ __align__(16) unsigned      g_qfw1s[128*1024];  // spread [w(2op) | w(2op+1)<<16]
__device__ __align__(16) unsigned char g_qfw2[10*256];

__device__ __align__(16) float g_act1[NB*16*196];   // (b,16,14,14)
__device__ __align__(16) float g_act2[NB*32*49];    // (b,32,7,7)
__device__ __align__(16) float g_act3[NB*64*16];    // (b,64,4,4)
__device__ __align__(16) float g_fc1 [NB*256];

// ---------------- PDL ----------------
__device__ __forceinline__ void pdl_trigger() {
    asm volatile("griddepcontrol.launch_dependents;");
}
__device__ __forceinline__ void pdl_wait() {
    asm volatile("griddepcontrol.wait;" ::: "memory");
}

// ---------------- helpers ----------------
__device__ __forceinline__ float scale_from_bits(int idx) {
    float m = __int_as_float(g_maxbits[idx]);
    return __fdiv_rn(255.0f, fmaxf(m, 1e-6f));
}
__device__ __forceinline__ unsigned char quant1(float v, float s) {
    float r = rintf(__fmul_rn(v, s));            // half-even == jnp.round
    r = fminf(fmaxf(r, 0.0f), 255.0f);
    return (unsigned char)(int)r;
}
__device__ __forceinline__ void warp_scale_pmax(int slot, float* out) {
    unsigned v = __float_as_uint(g_pmax[slot*32 + (threadIdx.x & 31)]);
    v = __reduce_max_sync(0xFFFFFFFFu, v);
    if ((threadIdx.x & 31) == 0)
        *out = __fdiv_rn(255.0f, fmaxf(__uint_as_float(v), 1e-6f));
}
// sp = [a0 | a1<<16]; returns [(a0*w)>>8 | ((a1*w)>>8)<<16], exact
__device__ __forceinline__ unsigned mac2(unsigned sp, unsigned wv) {
    return __byte_perm(sp * wv, 0u, 0x4341);
}
struct Row3 { unsigned r0, r1, r2; };
__device__ __forceinline__ Row3 load_row3(const unsigned short* p) {
    const unsigned* q = (const unsigned*)p;
    Row3 r; r.r0 = q[0]; r.r1 = q[1]; r.r2 = q[2]; return r;
}
__device__ __forceinline__ void row_mac_r(const Row3 r, const unsigned* w5, unsigned& acc) {
    acc += mac2(r.r0, w5[0]);
    acc += mac2(__byte_perm(r.r0, r.r1, 0x5432), w5[1]);
    acc += mac2(r.r1, w5[2]);
    acc += mac2(__byte_perm(r.r1, r.r2, 0x5432), w5[3]);
    acc += mac2(r.r2, w5[4]);
}
__device__ __forceinline__ void row_mac(const Row3 r, const unsigned char* wp, unsigned& acc) {
    acc += mac2(r.r0, wp[0]);
    acc += mac2(__byte_perm(r.r0, r.r1, 0x5432), wp[1]);
    acc += mac2(r.r1, wp[2]);
    acc += mac2(__byte_perm(r.r1, r.r2, 0x5432), wp[3]);
    acc += mac2(r.r2, wp[4]);
}

// ---------------- k_maxA: maxima of x, w1 + reset activation slots ----------
__global__ void k_maxA(const float* __restrict__ x, const float* __restrict__ w1) {
    pdl_trigger();                               // let conv1 launch + prefetch early
    int idx = blockIdx.y, bx = blockIdx.x;
    const float* src; int n;
    if (idx == 0) { src = x;  n = NB*784; }
    else          { src = w1; n = 16*25;  }
    float m = 0.0f;
    for (int i = bx*blockDim.x + threadIdx.x; i < n; i += gridDim.x*blockDim.x)
        m = fmaxf(m, fabsf(src[i]));
    __shared__ int sm;
    if (threadIdx.x == 0) sm = 0;
    __syncthreads();
    atomicMax(&sm, __float_as_int(m));
    __syncthreads();
    if (threadIdx.x == 0) {
        g_pmax[idx*32 + bx] = __int_as_float(sm);
        if (idx == 0 && bx == 0) {
            g_maxbits[6] = 0; g_maxbits[7] = 0; g_maxbits[8] = 0; g_maxbits[9] = 0;
        }
    }
}

// ---------------- k_maxFW: maxima of fw1, fw2, w2, w3 (side stream) --------
__global__ void k_maxFW(const float* __restrict__ fw1, const float* __restrict__ fw2,
                        const float* __restrict__ w2,  const float* __restrict__ w3) {
    int idx = blockIdx.y, bx = blockIdx.x;
    const float* src; int n; int slot;
    switch (idx) {
        case 0: src = fw1; n = 256*1024; slot = 4; break;
        case 1: src = fw2; n = 10*256;   slot = 5; break;
        case 2: src = w2;  n = 32*400;   slot = 2; break;
        default:src = w3;  n = 64*800;   slot = 3; break;
    }
    float m = 0.0f;
    for (int i = bx*blockDim.x + threadIdx.x; i < n; i += gridDim.x*blockDim.x)
        m = fmaxf(m, fabsf(src[i]));
    __shared__ int sm;
    if (threadIdx.x == 0) sm = 0;
    __syncthreads();
    atomicMax(&sm, __float_as_int(m));
    __syncthreads();
    if (threadIdx.x == 0) g_pmax[slot*32 + bx] = __int_as_float(sm);
}

// ---------------- k_qfw: quantize fw1 (spread), fw2, w2, w3 (side stream) --
__global__ void k_qfw(const float* __restrict__ fw1, const float* __restrict__ fw2,
                      const float* __restrict__ w2,  const float* __restrict__ w3) {
    __shared__ float sc[4];                     // sfw1, sfw2, sw2, sw3
    int t = threadIdx.x;                        // 256
    if (t < 32) warp_scale_pmax(4, &sc[0]);
    else if (t < 64)  warp_scale_pmax(5, &sc[1]);
    else if (t < 96)  warp_scale_pmax(2, &sc[2]);
    else if (t < 128) warp_scale_pmax(3, &sc[3]);
    __syncthreads();
    float sfw1 = sc[0], sfw2 = sc[1], sw2s = sc[2], sw3s = sc[3];
    int blk = blockIdx.x;                       // 64 blocks
    int base = blk * 2048;                      // fw1: 64*2048 = 131072 uints
    for (int i = t; i < 2048; i += 256) {
        int gi = base + i, op = gi >> 10, k = gi & 1023;
        unsigned lo = quant1(fw1[(2*op)*1024 + k], sfw1);
        unsigned hi = quant1(fw1[(2*op+1)*1024 + k], sfw1);
        g_qfw1s[gi] = lo | (hi << 16);
    }
    if (t < 200) g_qw2[blk*200 + t] = quant1(w2[blk*200 + t], sw2s);   // 64*200
    for (int i = t; i < 800; i += 256)
        g_qw3[blk*800 + i] = quant1(w3[blk*800 + i], sw3s);            // 64*800
    if (blk < 10)
        g_qfw2[blk*256 + t] = quant1(fw2[blk*256 + t], sfw2);
}

// ---------------- conv1 (PDL): qx -> relu+pool -> act1 ----------------
// grid 256 = (b, og8 of 2 o), block 392
__global__ void k_conv1(const float* __restrict__ x, const float* __restrict__ w1,
                        const float* __restrict__ b1) {
    pdl_trigger();
    int blk = blockIdx.x; int b = blk >> 3, o0 = (blk & 7)*2;
    __shared__ unsigned short sa16[32*32];
    __shared__ unsigned char sw[2*32];
    __shared__ float sc[2];                     // sx, sw1
    __shared__ int smax;
    int t = threadIdx.x;                        // 392

    // --- independent prologue: prefetch floats, zero smem ---
    float xv0 = x[b*784 + t];
    float xv1 = x[b*784 + t + 392];             // 784 = 2*392 exactly
    float w1v = (t < 50) ? w1[o0*25 + t] : 0.0f;
    if (t == 0) smax = 0;
    for (int i = t; i < 512; i += 392) ((unsigned*)sa16)[i] = 0u;

    pdl_wait();                                 // k_maxA fully visible after this

    if (t < 32) warp_scale_pmax(0, &sc[0]);
    else if (t < 64) warp_scale_pmax(1, &sc[1]);
    __syncthreads();

    float sx = sc[0], sw1s = sc[1];
    {
        int r0 = t / 28, c0 = t - r0*28;
        sa16[(r0+2)*32 + (c0+2)] = quant1(xv0, sx);
        int i1 = t + 392;
        int r1 = i1 / 28, c1 = i1 - r1*28;
        sa16[(r1+2)*32 + (c1+2)] = quant1(xv1, sx);
    }
    if (t < 50) {
        int ol = t / 25, k = t - ol*25;
        sw[ol*32 + k] = quant1(w1v, sw1s);
    }
    __syncthreads();

    int ol = (t >= 196) ? 1 : 0;
    int pos = t - ol*196;
    int py = pos / 14, px = pos % 14;
    const unsigned char* wb = sw + ol*32;

    unsigned acc0 = 0, acc1 = 0;
    Row3 cur = load_row3(&sa16[(2*py)*32 + 2*px]);
    #pragma unroll
    for (int ky = 0; ky < 5; ky++) {
        Row3 nxt = load_row3(&sa16[(2*py + ky + 1)*32 + 2*px]);
        row_mac(cur, wb + ky*5, acc0);
        row_mac(nxt, wb + ky*5, acc1);
        cur = nxt;
    }
    int best = max(max((int)(acc0 & 0xFFFF), (int)(acc0 >> 16)),
                   max((int)(acc1 & 0xFFFF), (int)(acc1 >> 16)));
    int o = o0 + ol;
    float v = fmaxf((float)best + b1[o], 0.0f);
    g_act1[(b*16 + o)*196 + pos] = v;
    atomicMax(&smax, __float_as_int(v));
    __syncthreads();
    if (t == 0) atomicMax(&g_maxbits[6], smax);
}

// ---------------- conv2 (PDL, vec4 loads): act1 -> relu+pool -> act2 -------
// grid 256 = (b, og8 of 4 o), block 448 = o_l(4)x112 + ys(2)x56 + kc(8,2ch)x7 + xq(7)
__global__ void k_conv2(const float* __restrict__ b2) {
    pdl_trigger();
    int blk = blockIdx.x; int b = blk >> 3, o0 = (blk & 7)*4;
    __shared__ unsigned short sa16[16*18*20];   // ch stride 360 el, row 20 el
    __shared__ unsigned char swq[4*400];
    __shared__ int psum[8*4*14*14];             // [kc][o_l][y][x]
    __shared__ float sc1;
    __shared__ int smax;
    int t = threadIdx.x;                        // 448

    if (t == 0) smax = 0;
    for (int i = t; i < 2880; i += 448) ((unsigned*)sa16)[i] = 0u;

    pdl_wait();                                 // conv1's act1/maxbits visible

    if (t == 0) sc1 = scale_from_bits(6);
    __syncthreads();

    float sa1 = sc1;
    {
        const float4* src = (const float4*)(g_act1 + b*3136);
        for (int j = t; j < 784; j += 448) {    // 784 float4 = 3136 floats
            float4 v = src[j];
            int i0 = j*4;
            #pragma unroll
            for (int e = 0; e < 4; e++) {
                int ii = i0 + e;
                int ch = ii / 196, rem = ii - ch*196;
                int r = rem / 14, c = rem - r*14;
                float fv = (e == 0) ? v.x : (e == 1) ? v.y : (e == 2) ? v.z : v.w;
                sa16[ch*360 + (r+2)*20 + (c+2)] = quant1(fv, sa1);
            }
        }
    }
    if (t < 100) ((uint4*)swq)[t] = ((const uint4*)(g_qw2 + o0*400))[t];
    __syncthreads();

    {
        int o_l = t / 112, r = t - o_l*112;
        int ys = r / 56, r2 = r - ys*56;
        int kc = r2 / 7, xq = r2 - kc*7;
        int rbase = ys*7;                       // rows rbase..rbase+10, y rbase..rbase+6

        unsigned acc[7];
        #pragma unroll
        for (int j = 0; j < 7; j++) acc[j] = 0;

        #pragma unroll
        for (int cc = 0; cc < 2; cc++) {
            int ch = kc*2 + cc;
            const unsigned short* base = sa16 + ch*360 + xq*2;
            const unsigned char* wp = swq + o_l*400 + ch*25;
            unsigned w[25];
            #pragma unroll
            for (int i = 0; i < 25; i++) w[i] = wp[i];
            #pragma unroll
            for (int rr = 0; rr < 11; rr++) {
                Row3 row = load_row3(base + (rbase + rr)*20);
                #pragma unroll
                for (int ky = 0; ky < 5; ky++) {
                    int yr = rr - ky;
                    if (yr >= 0 && yr < 7) row_mac_r(row, w + ky*5, acc[yr]);
                }
            }
        }
        int pbase = ((kc*4 + o_l)*14 + rbase)*14 + xq*2;
        #pragma unroll
        for (int j = 0; j < 7; j++) {
            psum[pbase + j*14]     = acc[j] & 0xFFFF;
            psum[pbase + j*14 + 1] = acc[j] >> 16;
        }
    }
    __syncthreads();

    if (t < 196) {
        int o_r = t / 49, p = t - o_r*49;
        int py = p / 7, px = p - py*7;
        int best = INT_MIN_V;
        #pragma unroll
        for (int dy = 0; dy < 2; dy++) {
            #pragma unroll
            for (int dx = 0; dx < 2; dx++) {
                int yy = 2*py + dy, xx = 2*px + dx;
                int s = 0;
                #pragma unroll
                for (int k = 0; k < 8; k++)
                    s += psum[((k*4 + o_r)*14 + yy)*14 + xx];
                best = max(best, s);
            }
        }
        int o = o0 + o_r;
        float v = fmaxf((float)best + b2[o], 0.0f);
        g_act2[(b*32 + o)*49 + p] = v;
        atomicMax(&smax, __float_as_int(v));
    }
    __syncthreads();
    if (t == 0) atomicMax(&g_maxbits[7], smax);
}

// ---------------- conv3 (PDL, vec4 loads): act2 -> relu+pool(pad=1) -> act3
// grid 512 = (b, og16 of 4 o), block 512: t = o_l(4)*128 + ys(2)*64 + kc(16,2ch)*4 + xq(4)
__global__ void k_conv3(const float* __restrict__ b3) {
    pdl_trigger();
    int blk = blockIdx.x; int b = blk >> 4, o0 = (blk & 15)*4;
    __shared__ unsigned short sa16[32*11*12];   // ch stride 132 el, row 12 el
    __shared__ unsigned char swq[4*800];
    __shared__ int psum[16*4*56];               // [kc][o_l][y*8+x]
    __shared__ int stot[4*56];
    __shared__ float sc1;
    __shared__ int smax;
    int t = threadIdx.x;                        // 512

    if (t == 0) smax = 0;
    for (int i = t; i < 2112; i += 512) ((unsigned*)sa16)[i] = 0u;

    pdl_wait();                                 // conv2's act2/maxbits visible

    if (t == 0) sc1 = scale_from_bits(7);
    __syncthreads();

    float sa2 = sc1;
    if (t < 392) {                              // 392 float4 = 1568 floats
        float4 v = ((const float4*)(g_act2 + b*1568))[t];
        int i0 = t*4;
        #pragma unroll
        for (int e = 0; e < 4; e++) {
            int ii = i0 + e;
            int ch = ii / 49, rem = ii - ch*49;
            int r = rem / 7, c = rem - r*7;
            float fv = (e == 0) ? v.x : (e == 1) ? v.y : (e == 2) ? v.z : v.w;
            sa16[ch*132 + (r+2)*12 + (c+2)] = quant1(fv, sa2);
        }
    }
    if (t < 200) ((uint4*)swq)[t] = ((const uint4*)(g_qw3 + o0*800))[t];
    __syncthreads();

    {
        int o_l = t >> 7, r7 = t & 127;
        int ys = r7 >> 6, kc = (r7 >> 2) & 15, xq = r7 & 3;
        int rbase = ys*3;                       // rows rbase..rbase+7; y rbase..rbase+3
        unsigned acc[4];
        #pragma unroll
        for (int j = 0; j < 4; j++) acc[j] = 0;

        #pragma unroll
        for (int cc = 0; cc < 2; cc++) {
            int ch = kc*2 + cc;
            const unsigned short* base = sa16 + ch*132 + xq*2;
            const unsigned char* wp = swq + o_l*800 + ch*25;
            unsigned w[25];
            #pragma unroll
            for (int i = 0; i < 25; i++) w[i] = wp[i];
            #pragma unroll
            for (int rr = 0; rr < 8; rr++) {
                Row3 row = load_row3(base + (rbase + rr)*12);
                #pragma unroll
                for (int ky = 0; ky < 5; ky++) {
                    int yr = rr - ky;
                    if (yr >= 0 && yr < 4) row_mac_r(row, w + ky*5, acc[yr]);
                }
            }
        }
        int pbase = (kc*4 + o_l)*56 + rbase*8 + xq*2;
        #pragma unroll
        for (int j = 0; j < 4; j++) {
            if (j >= ys) {                      // ys=1 skips duplicate y=3
                psum[pbase + j*8]     = acc[j] & 0xFFFF;
                psum[pbase + j*8 + 1] = acc[j] >> 16;   // x=7 garbage, never pooled
            }
        }
    }
    __syncthreads();

    if (t < 224) {                              // kc-sum
        int o_r = t / 56, p = t - o_r*56;
        int s = 0;
        #pragma unroll
        for (int k = 0; k < 16; k++) s += psum[(k*4 + o_r)*56 + p];
        stot[o_r*56 + p] = s;
    }
    __syncthreads();

    if (t < 64) {
        int o_r = t >> 4, idx2 = t & 15;
        int py = idx2 >> 2, px = idx2 & 3;
        int best = INT_MIN_V;
        #pragma unroll
        for (int dy = 0; dy < 2; dy++) {
            int ry = 2*py - 1 + dy;
            if ((unsigned)ry >= 7u) continue;
            #pragma unroll
            for (int dx = 0; dx < 2; dx++) {
                int rx = 2*px - 1 + dx;
                if ((unsigned)rx >= 7u) continue;
                best = max(best, stot[o_r*56 + ry*8 + rx]);
            }
        }
        int o = o0 + o_r;
        float v = fmaxf((float)best + b3[o], 0.0f);
        g_act3[b*1024 + o*16 + idx2] = v;
        atomicMax(&smax, __float_as_int(v));
    }
    __syncthreads();
    if (t == 0) atomicMax(&g_maxbits[8], smax);
}

// ---------------- fc1 (PDL, vec4): spread-weight dual-output dot ------------
// grid 256 = (b, og8 of 16 o-pairs), block 256 = op_l(16) x ks(16, 64 k each)
__global__ void k_fc1(const float* __restrict__ fb1) {
    pdl_trigger();
    int blk = blockIdx.x; int b = blk >> 3, og = blk & 7;
    __shared__ unsigned char qa[1024];
    __shared__ int red[512];
    __shared__ float sc1;
    __shared__ int smax;
    int t = threadIdx.x;                        // 256

    if (t == 0) smax = 0;
    pdl_wait();                                 // conv3's act3/maxbits visible
    if (t == 0) sc1 = scale_from_bits(8);
    __syncthreads();
    float sa3 = sc1;
    {
        float4 v = ((const float4*)(g_act3 + b*1024))[t];   // 256 float4 = 1024
        uchar4 q;
        q.x = quant1(v.x, sa3); q.y = quant1(v.y, sa3);
        q.z = quant1(v.z, sa3); q.w = quant1(v.w, sa3);
        ((uchar4*)qa)[t] = q;
    }
    __syncthreads();

    int op_l = t >> 4, ks = t & 15;
    int op = og*16 + op_l;
    const uint4* wp = (const uint4*)(g_qfw1s + op*1024 + ks*64);
    const unsigned* ap = (const unsigned*)(qa + ks*64);
    unsigned acc = 0;
    #pragma unroll
    for (int i = 0; i < 16; i++) {
        uint4 w = wp[i];
        unsigned au = ap[i];
        acc += __byte_perm(w.x * __byte_perm(au, 0u, 0x4440), 0u, 0x4341);
        acc += __byte_perm(w.y * __byte_perm(au, 0u, 0x4441), 0u, 0x4341);
        acc += __byte_perm(w.z * __byte_perm(au, 0u, 0x4442), 0u, 0x4341);
        acc += __byte_perm(w.w * __byte_perm(au, 0u, 0x4443), 0u, 0x4341);
    }
    red[op_l*16 + ks]       = acc & 0xFFFF;
    red[256 + op_l*16 + ks] = acc >> 16;
    __syncthreads();

    if (t < 32) {
        int op_r = t >> 1, parity = t & 1;
        int base = parity*256 + op_r*16;
        int s = 0;
        #pragma unroll
        for (int i = 0; i < 16; i++) s += red[base + i];
        int o = og*32 + op_r*2 + parity;
        float v = fmaxf((float)s + fb1[o], 0.0f);
        g_fc1[b*256 + o] = v;
        atomicMax(&smax, __float_as_int(v));
    }
    __syncthreads();
    if (t == 0) atomicMax(&g_maxbits[9], smax);
}

// ---------------- fc2 + log_softmax (PDL). grid 32, block 128 --------------
__global__ void k_fc2(const float* __restrict__ fb2, float* __restrict__ out) {
    int b = blockIdx.x;
    __shared__ unsigned char qa[256];
    __shared__ int red[80];
    __shared__ float vals[10];
    __shared__ float mred[2];
    __shared__ float sc1;
    int t = threadIdx.x;                        // 128

    pdl_wait();                                 // fc1's g_fc1/maxbits visible
    if (t == 0) sc1 = scale_from_bits(9);
    __syncthreads();
    float sf1 = sc1;
    for (int i = t; i < 256; i += 128) qa[i] = quant1(g_fc1[b*256 + i], sf1);
    __syncthreads();

    if (t < 80) {
        int o = t >> 3, ks = t & 7;
        const unsigned char* wp = g_qfw2 + o*256 + ks*32;
        const unsigned char* ap = qa + ks*32;
        int s = 0;
        #pragma unroll
        for (int k = 0; k < 32; k++) s += (ap[k] * wp[k]) >> 8;
        red[t] = s;
    }
    __syncthreads();
    if (t < 10) {
        int s = 0;
        #pragma unroll
        for (int i = 0; i < 8; i++) s += red[t*8 + i];
        vals[t] = (float)s + fb2[t];
    }
    __syncthreads();
    if (t == 0) {
        float m = vals[0];
        #pragma unroll
        for (int i = 1; i < 10; i++) m = fmaxf(m, vals[i]);
        float se = 0.0f;
        #pragma unroll
        for (int i = 0; i < 10; i++) se += expf(vals[i] - m);
        mred[0] = m; mred[1] = logf(se);
    }
    __syncthreads();
    if (t < 10) out[b*10 + t] = vals[t] - mred[0] - mred[1];
}

// ---------------- launch ----------------
static inline void launch_pdl(void* fn, dim3 grid, dim3 block, void** args) {
    cudaLaunchAttribute attr[1];
    attr[0].id = cudaLaunchAttributeProgrammaticStreamSerialization;
    attr[0].val.programmaticStreamSerializationAllowed = 1;
    cudaLaunchConfig_t cfg = {};
    cfg.gridDim = grid; cfg.blockDim = block;
    cfg.dynamicSmemBytes = 0; cfg.stream = 0;
    cfg.attrs = attr; cfg.numAttrs = 1;
    cudaLaunchKernelExC(&cfg, fn, args);
}

extern "C" void kernel_launch(void* const* d_in, const int* in_sizes, int n_in,
                              void* d_out, int out_size) {
    const float* x   = (const float*)d_in[0];
    // d_in[1] = lut — unused: lut[a][b] == (a*b)>>8 exactly
    const float* w1  = (const float*)d_in[2];
    const float* b1  = (const float*)d_in[3];
    const float* w2  = (const float*)d_in[4];
    const float* b2  = (const float*)d_in[5];
    const float* w3  = (const float*)d_in[6];
    const float* b3  = (const float*)d_in[7];
    const float* fw1 = (const float*)d_in[8];
    const float* fb1 = (const float*)d_in[9];
    const float* fw2 = (const float*)d_in[10];
    const float* fb2 = (const float*)d_in[11];
    float* out = (float*)d_out;

    static cudaStream_t s_side = 0;
    static cudaEvent_t ev_fork = 0, ev_join = 0;
    if (s_side == 0) {
        cudaStreamCreateWithFlags(&s_side, cudaStreamNonBlocking);
        cudaEventCreateWithFlags(&ev_fork, cudaEventDisableTiming);
        cudaEventCreateWithFlags(&ev_join, cudaEventDisableTiming);
    }

    // side branch: fw1/fw2/w2/w3 quant path (w2/w3 needed from conv2 on)
    cudaEventRecord(ev_fork, 0);
    cudaStreamWaitEvent(s_side, ev_fork, 0);
    k_maxFW<<<dim3(32, 4), 256, 0, s_side>>>(fw1, fw2, w2, w3);
    k_qfw  <<<64, 256, 0, s_side>>>(fw1, fw2, w2, w3);
    cudaEventRecord(ev_join, s_side);

    // main chain with PDL at every boundary
    k_maxA <<<dim3(32, 2), 256>>>(x, w1);
    {
        void* a[] = { (void*)&x, (void*)&w1, (void*)&b1 };
        launch_pdl((void*)k_conv1, dim3(256), dim3(392), a);
    }
    cudaStreamWaitEvent(0, ev_join, 0);         // side must finish before conv2 reads qw2
    {
        void* a[] = { (void*)&b2 };
        launch_pdl((void*)k_conv2, dim3(256), dim3(448), a);
    }
    {
        void* a[] = { (void*)&b3 };
        launch_pdl((void*)k_conv3, dim3(512), dim3(512), a);
    }
    {
        void* a[] = { (void*)&fb1 };
        launch_pdl((void*)k_fc1, dim3(256), dim3(256), a);
    }
    {
        void* a[] = { (void*)&fb2, (void*)&out };
        launch_pdl((void*)k_fc2, dim3(32), dim3(128), a);
    }
}

// round 14
// speedup vs baseline: 1.1460x; 1.1460x over previous
#include <cuda_runtime.h>
#include <math.h>

#define NB 32
#define INT_MIN_V ((int)0x80000000)

// pmax slots (inputs): 0=x 1=w1 2=w2 3=w3 4=fw1 5=fw2
// maxbits slots (activations, atomic): 6=A1 7=A2 8=A3 9=F1
__device__ float g_pmax[6*32];
__device__ int   g_maxbits[10];

__device__ __align__(16) unsigned char g_qw2 [32*400];
__device__ __align__(16) unsigned char g_qw3 [64*800];
__device__ __align__(16) unsigned      g_qfw1s[128*1024];  // spread [w(2op) | w(2op+1)<<16]
__device__ __align__(16) unsigned char g_qfw2[10*256];

__device__ __align__(16) float g_act1[NB*16*196];   // (b,16,14,14)
__device__ __align__(16) float g_act2[NB*32*49];    // (b,32,7,7)
__device__ __align__(16) float g_act3[NB*64*16];    // (b,64,4,4)
__device__ __align__(16) float g_fc1 [NB*256];

// ---------------- PDL ----------------
__device__ __forceinline__ void pdl_trigger() {
    asm volatile("griddepcontrol.launch_dependents;");
}
__device__ __forceinline__ void pdl_wait() {
    asm volatile("griddepcontrol.wait;" ::: "memory");
}

// ---------------- helpers ----------------
__device__ __forceinline__ float scale_from_bits(int idx) {
    float m = __int_as_float(g_maxbits[idx]);
    return __fdiv_rn(255.0f, fmaxf(m, 1e-6f));
}
__device__ __forceinline__ unsigned char quant1(float v, float s) {
    float r = rintf(__fmul_rn(v, s));            // half-even == jnp.round
    r = fminf(fmaxf(r, 0.0f), 255.0f);
    return (unsigned char)(int)r;
}
__device__ __forceinline__ void warp_scale_pmax(int slot, float* out) {
    unsigned v = __float_as_uint(g_pmax[slot*32 + (threadIdx.x & 31)]);
    v = __reduce_max_sync(0xFFFFFFFFu, v);
    if ((threadIdx.x & 31) == 0)
        *out = __fdiv_rn(255.0f, fmaxf(__uint_as_float(v), 1e-6f));
}
// sp = [a0 | a1<<16]; returns [(a0*w)>>8 | ((a1*w)>>8)<<16], exact
__device__ __forceinline__ unsigned mac2(unsigned sp, unsigned wv) {
    return __byte_perm(sp * wv, 0u, 0x4341);
}
struct Row3 { unsigned r0, r1, r2; };
__device__ __forceinline__ Row3 load_row3(const unsigned short* p) {
    const unsigned* q = (const unsigned*)p;
    Row3 r; r.r0 = q[0]; r.r1 = q[1]; r.r2 = q[2]; return r;
}
__device__ __forceinline__ void row_mac_r(const Row3 r, const unsigned* w5, unsigned& acc) {
    acc += mac2(r.r0, w5[0]);
    acc += mac2(__byte_perm(r.r0, r.r1, 0x5432), w5[1]);
    acc += mac2(r.r1, w5[2]);
    acc += mac2(__byte_perm(r.r1, r.r2, 0x5432), w5[3]);
    acc += mac2(r.r2, w5[4]);
}
__device__ __forceinline__ void row_mac(const Row3 r, const unsigned char* wp, unsigned& acc) {
    acc += mac2(r.r0, wp[0]);
    acc += mac2(__byte_perm(r.r0, r.r1, 0x5432), wp[1]);
    acc += mac2(r.r1, wp[2]);
    acc += mac2(__byte_perm(r.r1, r.r2, 0x5432), wp[3]);
    acc += mac2(r.r2, wp[4]);
}

// ---------------- k_maxA: maxima of x,w1,w2,w3 + reset activation slots -----
__global__ void k_maxA(const float* __restrict__ x,  const float* __restrict__ w1,
                       const float* __restrict__ w2, const float* __restrict__ w3) {
    pdl_trigger();                               // let conv1 launch + prefetch early
    int idx = blockIdx.y, bx = blockIdx.x;
    const float* src; int n;
    switch (idx) {
        case 0: src = x;  n = NB*784; break;
        case 1: src = w1; n = 16*25;  break;
        case 2: src = w2; n = 32*400; break;
        default:src = w3; n = 64*800; break;
    }
    float m = 0.0f;
    for (int i = bx*blockDim.x + threadIdx.x; i < n; i += gridDim.x*blockDim.x)
        m = fmaxf(m, fabsf(src[i]));
    __shared__ int sm;
    if (threadIdx.x == 0) sm = 0;
    __syncthreads();
    atomicMax(&sm, __float_as_int(m));
    __syncthreads();
    if (threadIdx.x == 0) {
        g_pmax[idx*32 + bx] = __int_as_float(sm);
        if (idx == 0 && bx == 0) {
            g_maxbits[6] = 0; g_maxbits[7] = 0; g_maxbits[8] = 0; g_maxbits[9] = 0;
        }
    }
}

// ---------------- k_maxFW: maxima of fw1, fw2 (side stream) ----------------
__global__ void k_maxFW(const float* __restrict__ fw1, const float* __restrict__ fw2) {
    int idx = blockIdx.y, bx = blockIdx.x;
    const float* src; int n; int slot;
    if (idx == 0) { src = fw1; n = 256*1024; slot = 4; }
    else          { src = fw2; n = 10*256;   slot = 5; }
    float m = 0.0f;
    for (int i = bx*blockDim.x + threadIdx.x; i < n; i += gridDim.x*blockDim.x)
        m = fmaxf(m, fabsf(src[i]));
    __shared__ int sm;
    if (threadIdx.x == 0) sm = 0;
    __syncthreads();
    atomicMax(&sm, __float_as_int(m));
    __syncthreads();
    if (threadIdx.x == 0) g_pmax[slot*32 + bx] = __int_as_float(sm);
}

// ---------------- k_qfw: quantize fw1 (spread) + fw2 (side stream) ---------
__global__ void k_qfw(const float* __restrict__ fw1, const float* __restrict__ fw2) {
    __shared__ float sc[2];
    int t = threadIdx.x;                        // 256
    if (t < 32) warp_scale_pmax(4, &sc[0]);
    else if (t < 64) warp_scale_pmax(5, &sc[1]);
    __syncthreads();
    float sfw1 = sc[0], sfw2 = sc[1];
    int base = blockIdx.x * 2048;               // 64 blocks * 2048 = 131072 uints
    for (int i = t; i < 2048; i += 256) {
        int gi = base + i, op = gi >> 10, k = gi & 1023;
        unsigned lo = quant1(fw1[(2*op)*1024 + k], sfw1);
        unsigned hi = quant1(fw1[(2*op+1)*1024 + k], sfw1);
        g_qfw1s[gi] = lo | (hi << 16);
    }
    if (blockIdx.x < 10)
        g_qfw2[blockIdx.x*256 + t] = quant1(fw2[blockIdx.x*256 + t], sfw2);
}

// ---------------- conv1 + quantize w2/w3 slices (PDL) ----------------
// grid 256 = (b, og8 of 2 o), block 392
__global__ void k_conv1(const float* __restrict__ x, const float* __restrict__ w1,
                        const float* __restrict__ b1, const float* __restrict__ w2,
                        const float* __restrict__ w3) {
    pdl_trigger();
    int blk = blockIdx.x; int b = blk >> 3, o0 = (blk & 7)*2;
    __shared__ unsigned short sa16[32*32];
    __shared__ unsigned char sw[2*32];
    __shared__ float sc[4];                     // sx, sw1, sw2, sw3
    __shared__ int smax;
    int t = threadIdx.x;                        // 392

    // --- independent prologue: prefetch floats, zero smem ---
    float xv0 = x[b*784 + t];
    float xv1 = x[b*784 + t + 392];             // 784 = 2*392 exactly
    float w1v = (t < 50)  ? w1[o0*25 + t]    : 0.0f;
    float w2v = (t < 50)  ? w2[blk*50 + t]   : 0.0f;
    float w3v = (t < 200) ? w3[blk*200 + t]  : 0.0f;
    if (t == 0) smax = 0;
    for (int i = t; i < 512; i += 392) ((unsigned*)sa16)[i] = 0u;

    pdl_wait();                                 // k_maxA fully visible after this

    if (t < 32) warp_scale_pmax(0, &sc[0]);
    else if (t < 64)  warp_scale_pmax(1, &sc[1]);
    else if (t < 96)  warp_scale_pmax(2, &sc[2]);
    else if (t < 128) warp_scale_pmax(3, &sc[3]);
    __syncthreads();

    float sx = sc[0], sw1s = sc[1], sw2s = sc[2], sw3s = sc[3];
    {
        int r0 = t / 28, c0 = t - r0*28;
        sa16[(r0+2)*32 + (c0+2)] = quant1(xv0, sx);
        int i1 = t + 392;
        int r1 = i1 / 28, c1 = i1 - r1*28;
        sa16[(r1+2)*32 + (c1+2)] = quant1(xv1, sx);
    }
    if (t < 50) {
        int ol = t / 25, k = t - ol*25;
        sw[ol*32 + k] = quant1(w1v, sw1s);
        g_qw2[blk*50 + t] = quant1(w2v, sw2s);
    }
    if (t < 200) g_qw3[blk*200 + t] = quant1(w3v, sw3s);
    __syncthreads();

    int ol = (t >= 196) ? 1 : 0;
    int pos = t - ol*196;
    int py = pos / 14, px = pos % 14;
    const unsigned char* wb = sw + ol*32;

    unsigned acc0 = 0, acc1 = 0;
    Row3 cur = load_row3(&sa16[(2*py)*32 + 2*px]);
    #pragma unroll
    for (int ky = 0; ky < 5; ky++) {
        Row3 nxt = load_row3(&sa16[(2*py + ky + 1)*32 + 2*px]);
        row_mac(cur, wb + ky*5, acc0);
        row_mac(nxt, wb + ky*5, acc1);
        cur = nxt;
    }
    int best = max(max((int)(acc0 & 0xFFFF), (int)(acc0 >> 16)),
                   max((int)(acc1 & 0xFFFF), (int)(acc1 >> 16)));
    int o = o0 + ol;
    float v = fmaxf((float)best + b1[o], 0.0f);
    g_act1[(b*16 + o)*196 + pos] = v;
    atomicMax(&smax, __float_as_int(v));
    __syncthreads();
    if (t == 0) atomicMax(&g_maxbits[6], smax);
}

// ---------------- conv2 (PDL, vec4 loads): act1 -> relu+pool -> act2 -------
// grid 256 = (b, og8 of 4 o), block 448 = o_l(4)x112 + ys(2)x56 + kc(8,2ch)x7 + xq(7)
__global__ void k_conv2(const float* __restrict__ b2) {
    pdl_trigger();
    int blk = blockIdx.x; int b = blk >> 3, o0 = (blk & 7)*4;
    __shared__ unsigned short sa16[16*18*20];   // ch stride 360 el, row 20 el
    __shared__ unsigned char swq[4*400];
    __shared__ int psum[8*4*14*14];             // [kc][o_l][y][x]
    __shared__ float sc1;
    __shared__ int smax;
    int t = threadIdx.x;                        // 448

    if (t == 0) smax = 0;
    for (int i = t; i < 2880; i += 448) ((unsigned*)sa16)[i] = 0u;

    pdl_wait();                                 // conv1's act1/qw2/maxbits visible

    if (t == 0) sc1 = scale_from_bits(6);
    __syncthreads();

    float sa1 = sc1;
    {
        const float4* src = (const float4*)(g_act1 + b*3136);
        for (int j = t; j < 784; j += 448) {    // 784 float4 = 3136 floats
            float4 v = src[j];
            int i0 = j*4;
            #pragma unroll
            for (int e = 0; e < 4; e++) {
                int ii = i0 + e;
                int ch = ii / 196, rem = ii - ch*196;
                int r = rem / 14, c = rem - r*14;
                float fv = (e == 0) ? v.x : (e == 1) ? v.y : (e == 2) ? v.z : v.w;
                sa16[ch*360 + (r+2)*20 + (c+2)] = quant1(fv, sa1);
            }
        }
    }
    if (t < 100) ((uint4*)swq)[t] = ((const uint4*)(g_qw2 + o0*400))[t];
    __syncthreads();

    {
        int o_l = t / 112, r = t - o_l*112;
        int ys = r / 56, r2 = r - ys*56;
        int kc = r2 / 7, xq = r2 - kc*7;
        int rbase = ys*7;                       // rows rbase..rbase+10, y rbase..rbase+6

        unsigned acc[7];
        #pragma unroll
        for (int j = 0; j < 7; j++) acc[j] = 0;

        #pragma unroll
        for (int cc = 0; cc < 2; cc++) {
            int ch = kc*2 + cc;
            const unsigned short* base = sa16 + ch*360 + xq*2;
            const unsigned char* wp = swq + o_l*400 + ch*25;
            unsigned w[25];
            #pragma unroll
            for (int i = 0; i < 25; i++) w[i] = wp[i];
            #pragma unroll
            for (int rr = 0; rr < 11; rr++) {
                Row3 row = load_row3(base + (rbase + rr)*20);
                #pragma unroll
                for (int ky = 0; ky < 5; ky++) {
                    int yr = rr - ky;
                    if (yr >= 0 && yr < 7) row_mac_r(row, w + ky*5, acc[yr]);
                }
            }
        }
        int pbase = ((kc*4 + o_l)*14 + rbase)*14 + xq*2;
        #pragma unroll
        for (int j = 0; j < 7; j++) {
            psum[pbase + j*14]     = acc[j] & 0xFFFF;
            psum[pbase + j*14 + 1] = acc[j] >> 16;
        }
    }
    __syncthreads();

    if (t < 196) {
        int o_r = t / 49, p = t - o_r*49;
        int py = p / 7, px = p - py*7;
        int best = INT_MIN_V;
        #pragma unroll
        for (int dy = 0; dy < 2; dy++) {
            #pragma unroll
            for (int dx = 0; dx < 2; dx++) {
                int yy = 2*py + dy, xx = 2*px + dx;
                int s = 0;
                #pragma unroll
                for (int k = 0; k < 8; k++)
                    s += psum[((k*4 + o_r)*14 + yy)*14 + xx];
                best = max(best, s);
            }
        }
        int o = o0 + o_r;
        float v = fmaxf((float)best + b2[o], 0.0f);
        g_act2[(b*32 + o)*49 + p] = v;
        atomicMax(&smax, __float_as_int(v));
    }
    __syncthreads();
    if (t == 0) atomicMax(&g_maxbits[7], smax);
}

// ---------------- conv3 (PDL, vec4 loads): act2 -> relu+pool(pad=1) -> act3
// grid 512 = (b, og16 of 4 o), block 512: t = o_l(4)*128 + ys(2)*64 + kc(16,2ch)*4 + xq(4)
__global__ void k_conv3(const float* __restrict__ b3) {
    pdl_trigger();
    int blk = blockIdx.x; int b = blk >> 4, o0 = (blk & 15)*4;
    __shared__ unsigned short sa16[32*11*12];   // ch stride 132 el, row 12 el
    __shared__ unsigned char swq[4*800];
    __shared__ int psum[16*4*56];               // [kc][o_l][y*8+x]
    __shared__ int stot[4*56];
    __shared__ float sc1;
    __shared__ int smax;
    int t = threadIdx.x;                        // 512

    if (t == 0) smax = 0;
    for (int i = t; i < 2112; i += 512) ((unsigned*)sa16)[i] = 0u;

    pdl_wait();                                 // conv2's act2/maxbits visible

    if (t == 0) sc1 = scale_from_bits(7);
    __syncthreads();

    float sa2 = sc1;
    if (t < 392) {                              // 392 float4 = 1568 floats
        float4 v = ((const float4*)(g_act2 + b*1568))[t];
        int i0 = t*4;
        #pragma unroll
        for (int e = 0; e < 4; e++) {
            int ii = i0 + e;
            int ch = ii / 49, rem = ii - ch*49;
            int r = rem / 7, c = rem - r*7;
            float fv = (e == 0) ? v.x : (e == 1) ? v.y : (e == 2) ? v.z : v.w;
            sa16[ch*132 + (r+2)*12 + (c+2)] = quant1(fv, sa2);
        }
    }
    if (t < 200) ((uint4*)swq)[t] = ((const uint4*)(g_qw3 + o0*800))[t];
    __syncthreads();

    {
        int o_l = t >> 7, r7 = t & 127;
        int ys = r7 >> 6, kc = (r7 >> 2) & 15, xq = r7 & 3;
        int rbase = ys*3;                       // rows rbase..rbase+7; y rbase..rbase+3
        unsigned acc[4];
        #pragma unroll
        for (int j = 0; j < 4; j++) acc[j] = 0;

        #pragma unroll
        for (int cc = 0; cc < 2; cc++) {
            int ch = kc*2 + cc;
            const unsigned short* base = sa16 + ch*132 + xq*2;
            const unsigned char* wp = swq + o_l*800 + ch*25;
            unsigned w[25];
            #pragma unroll
            for (int i = 0; i < 25; i++) w[i] = wp[i];
            #pragma unroll
            for (int rr = 0; rr < 8; rr++) {
                Row3 row = load_row3(base + (rbase + rr)*12);
                #pragma unroll
                for (int ky = 0; ky < 5; ky++) {
                    int yr = rr - ky;
                    if (yr >= 0 && yr < 4) row_mac_r(row, w + ky*5, acc[yr]);
                }
            }
        }
        int pbase = (kc*4 + o_l)*56 + rbase*8 + xq*2;
        #pragma unroll
        for (int j = 0; j < 4; j++) {
            if (j >= ys) {                      // ys=1 skips duplicate y=3
                psum[pbase + j*8]     = acc[j] & 0xFFFF;
                psum[pbase + j*8 + 1] = acc[j] >> 16;   // x=7 garbage, never pooled
            }
        }
    }
    __syncthreads();

    if (t < 224) {                              // kc-sum
        int o_r = t / 56, p = t - o_r*56;
        int s = 0;
        #pragma unroll
        for (int k = 0; k < 16; k++) s += psum[(k*4 + o_r)*56 + p];
        stot[o_r*56 + p] = s;
    }
    __syncthreads();

    if (t < 64) {
        int o_r = t >> 4, idx2 = t & 15;
        int py = idx2 >> 2, px = idx2 & 3;
        int best = INT_MIN_V;
        #pragma unroll
        for (int dy = 0; dy < 2; dy++) {
            int ry = 2*py - 1 + dy;
            if ((unsigned)ry >= 7u) continue;
            #pragma unroll
            for (int dx = 0; dx < 2; dx++) {
                int rx = 2*px - 1 + dx;
                if ((unsigned)rx >= 7u) continue;
                best = max(best, stot[o_r*56 + ry*8 + rx]);
            }
        }
        int o = o0 + o_r;
        float v = fmaxf((float)best + b3[o], 0.0f);
        g_act3[b*1024 + o*16 + idx2] = v;
        atomicMax(&smax, __float_as_int(v));
    }
    __syncthreads();
    if (t == 0) atomicMax(&g_maxbits[8], smax);
}

// ---------------- fc1 (PDL, vec4): spread-weight dual-output dot ------------
// grid 256 = (b, og8 of 16 o-pairs), block 256 = op_l(16) x ks(16, 64 k each)
__global__ void k_fc1(const float* __restrict__ fb1) {
    pdl_trigger();
    int blk = blockIdx.x; int b = blk >> 3, og = blk & 7;
    __shared__ unsigned char qa[1024];
    __shared__ int red[512];
    __shared__ float sc1;
    __shared__ int smax;
    int t = threadIdx.x;                        // 256

    if (t == 0) smax = 0;
    pdl_wait();                                 // conv3's act3/maxbits visible
    if (t == 0) sc1 = scale_from_bits(8);
    __syncthreads();
    float sa3 = sc1;
    {
        float4 v = ((const float4*)(g_act3 + b*1024))[t];   // 256 float4 = 1024
        uchar4 q;
        q.x = quant1(v.x, sa3); q.y = quant1(v.y, sa3);
        q.z = quant1(v.z, sa3); q.w = quant1(v.w, sa3);
        ((uchar4*)qa)[t] = q;
    }
    __syncthreads();

    int op_l = t >> 4, ks = t & 15;
    int op = og*16 + op_l;
    const uint4* wp = (const uint4*)(g_qfw1s + op*1024 + ks*64);
    const unsigned* ap = (const unsigned*)(qa + ks*64);
    unsigned acc = 0;
    #pragma unroll
    for (int i = 0; i < 16; i++) {
        uint4 w = wp[i];
        unsigned au = ap[i];
        acc += __byte_perm(w.x * __byte_perm(au, 0u, 0x4440), 0u, 0x4341);
        acc += __byte_perm(w.y * __byte_perm(au, 0u, 0x4441), 0u, 0x4341);
        acc += __byte_perm(w.z * __byte_perm(au, 0u, 0x4442), 0u, 0x4341);
        acc += __byte_perm(w.w * __byte_perm(au, 0u, 0x4443), 0u, 0x4341);
    }
    red[op_l*16 + ks]       = acc & 0xFFFF;
    red[256 + op_l*16 + ks] = acc >> 16;
    __syncthreads();

    if (t < 32) {
        int op_r = t >> 1, parity = t & 1;
        int base = parity*256 + op_r*16;
        int s = 0;
        #pragma unroll
        for (int i = 0; i < 16; i++) s += red[base + i];
        int o = og*32 + op_r*2 + parity;
        float v = fmaxf((float)s + fb1[o], 0.0f);
        g_fc1[b*256 + o] = v;
        atomicMax(&smax, __float_as_int(v));
    }
    __syncthreads();
    if (t == 0) atomicMax(&g_maxbits[9], smax);
}

// ---------------- fc2 + log_softmax (PDL). grid 32, block 128 --------------
__global__ void k_fc2(const float* __restrict__ fb2, float* __restrict__ out) {
    int b = blockIdx.x;
    __shared__ unsigned char qa[256];
    __shared__ int red[80];
    __shared__ float vals[10];
    __shared__ float mred[2];
    __shared__ float sc1;
    int t = threadIdx.x;                        // 128

    pdl_wait();                                 // fc1's g_fc1/maxbits visible
    if (t == 0) sc1 = scale_from_bits(9);
    __syncthreads();
    float sf1 = sc1;
    for (int i = t; i < 256; i += 128) qa[i] = quant1(g_fc1[b*256 + i], sf1);
    __syncthreads();

    if (t < 80) {
        int o = t >> 3, ks = t & 7;
        const unsigned char* wp = g_qfw2 + o*256 + ks*32;
        const unsigned char* ap = qa + ks*32;
        int s = 0;
        #pragma unroll
        for (int k = 0; k < 32; k++) s += (ap[k] * wp[k]) >> 8;
        red[t] = s;
    }
    __syncthreads();
    if (t < 10) {
        int s = 0;
        #pragma unroll
        for (int i = 0; i < 8; i++) s += red[t*8 + i];
        vals[t] = (float)s + fb2[t];
    }
    __syncthreads();
    if (t == 0) {
        float m = vals[0];
        #pragma unroll
        for (int i = 1; i < 10; i++) m = fmaxf(m, vals[i]);
        float se = 0.0f;
        #pragma unroll
        for (int i = 0; i < 10; i++) se += expf(vals[i] - m);
        mred[0] = m; mred[1] = logf(se);
    }
    __syncthreads();
    if (t < 10) out[b*10 + t] = vals[t] - mred[0] - mred[1];
}

// ---------------- launch ----------------
static inline void launch_pdl(void* fn, dim3 grid, dim3 block, void** args) {
    cudaLaunchAttribute attr[1];
    attr[0].id = cudaLaunchAttributeProgrammaticStreamSerialization;
    attr[0].val.programmaticStreamSerializationAllowed = 1;
    cudaLaunchConfig_t cfg = {};
    cfg.gridDim = grid; cfg.blockDim = block;
    cfg.dynamicSmemBytes = 0; cfg.stream = 0;
    cfg.attrs = attr; cfg.numAttrs = 1;
    cudaLaunchKernelExC(&cfg, fn, args);
}

extern "C" void kernel_launch(void* const* d_in, const int* in_sizes, int n_in,
                              void* d_out, int out_size) {
    const float* x   = (const float*)d_in[0];
    // d_in[1] = lut — unused: lut[a][b] == (a*b)>>8 exactly
    const float* w1  = (const float*)d_in[2];
    const float* b1  = (const float*)d_in[3];
    const float* w2  = (const float*)d_in[4];
    const float* b2  = (const float*)d_in[5];
    const float* w3  = (const float*)d_in[6];
    const float* b3  = (const float*)d_in[7];
    const float* fw1 = (const float*)d_in[8];
    const float* fb1 = (const float*)d_in[9];
    const float* fw2 = (const float*)d_in[10];
    const float* fb2 = (const float*)d_in[11];
    float* out = (float*)d_out;

    static cudaStream_t s_side = 0;
    static cudaEvent_t ev_fork = 0, ev_join = 0;
    if (s_side == 0) {
        cudaStreamCreateWithFlags(&s_side, cudaStreamNonBlocking);
        cudaEventCreateWithFlags(&ev_fork, cudaEventDisableTiming);
        cudaEventCreateWithFlags(&ev_join, cudaEventDisableTiming);
    }

    // side branch: fw1/fw2 quant path (needed only by fc1/fc2)
    cudaEventRecord(ev_fork, 0);
    cudaStreamWaitEvent(s_side, ev_fork, 0);
    k_maxFW<<<dim3(32, 2), 256, 0, s_side>>>(fw1, fw2);
    k_qfw  <<<64, 256, 0, s_side>>>(fw1, fw2);
    cudaEventRecord(ev_join, s_side);

    // main chain with PDL at every boundary
    k_maxA <<<dim3(32, 4), 256>>>(x, w1, w2, w3);
    {
        void* a[] = { (void*)&x, (void*)&w1, (void*)&b1, (void*)&w2, (void*)&w3 };
        launch_pdl((void*)k_conv1, dim3(256), dim3(392), a);
    }
    {
        void* a[] = { (void*)&b2 };
        launch_pdl((void*)k_conv2, dim3(256), dim3(448), a);
    }
    {
        void* a[] = { (void*)&b3 };
        launch_pdl((void*)k_conv3, dim3(512), dim3(512), a);
    }
    cudaStreamWaitEvent(0, ev_join, 0);         // join before fc needs g_qfw1s/g_qfw2
    {
        void* a[] = { (void*)&fb1 };
        launch_pdl((void*)k_fc1, dim3(256), dim3(256), a);
    }
    {
        void* a[] = { (void*)&fb2, (void*)&out };
        launch_pdl((void*)k_fc2, dim3(32), dim3(128), a);
    }
}

// round 15
// speedup vs baseline: 1.1746x; 1.0249x over previous
#include <cuda_runtime.h>
#include <math.h>

#define NB 32
#define INT_MIN_V ((int)0x80000000)

// pmax slots (inputs): 0=x 1=w1 2=w2 3=w3 4=fw1 5=fw2
// maxbits slots (activations, atomic): 6=A1 7=A2 8=A3 9=F1
__device__ float g_pmax[6*32];
__device__ int   g_maxbits[10];

__device__ __align__(16) unsigned char g_qw2 [32*400];
__device__ __align__(16) unsigned char g_qw3 [64*800];
__device__ __align__(16) unsigned      g_qfw1s[128*1024];  // spread [w(2op) | w(2op+1)<<16]
__device__ __align__(16) unsigned char g_qfw2[10*256];

__device__ __align__(16) float g_act1[NB*16*196];   // (b,16,14,14)
__device__ __align__(16) float g_act2[NB*32*49];    // (b,32,7,7)
__device__ __align__(16) float g_act3[NB*64*16];    // (b,64,4,4)
__device__ __align__(16) float g_fc1 [NB*256];

// ---------------- PDL ----------------
__device__ __forceinline__ void pdl_trigger() {
    asm volatile("griddepcontrol.launch_dependents;");
}
__device__ __forceinline__ void pdl_wait() {
    asm volatile("griddepcontrol.wait;" ::: "memory");
}

// ---------------- helpers ----------------
__device__ __forceinline__ float scale_from_bits(int idx) {
    float m = __int_as_float(g_maxbits[idx]);
    return __fdiv_rn(255.0f, fmaxf(m, 1e-6f));
}
__device__ __forceinline__ unsigned char quant1(float v, float s) {
    float r = rintf(__fmul_rn(v, s));            // half-even == jnp.round
    r = fminf(fmaxf(r, 0.0f), 255.0f);
    return (unsigned char)(int)r;
}
__device__ __forceinline__ void warp_scale_pmax(int slot, float* out) {
    unsigned v = __float_as_uint(g_pmax[slot*32 + (threadIdx.x & 31)]);
    v = __reduce_max_sync(0xFFFFFFFFu, v);
    if ((threadIdx.x & 31) == 0)
        *out = __fdiv_rn(255.0f, fmaxf(__uint_as_float(v), 1e-6f));
}
// sp = [a0 | a1<<16]; returns [(a0*w)>>8 | ((a1*w)>>8)<<16], exact
__device__ __forceinline__ unsigned mac2(unsigned sp, unsigned wv) {
    return __byte_perm(sp * wv, 0u, 0x4341);
}
struct Row3 { unsigned r0, r1, r2; };
__device__ __forceinline__ Row3 load_row3(const unsigned short* p) {
    const unsigned* q = (const unsigned*)p;
    Row3 r; r.r0 = q[0]; r.r1 = q[1]; r.r2 = q[2]; return r;
}
__device__ __forceinline__ void row_mac_r(const Row3 r, const unsigned* w5, unsigned& acc) {
    acc += mac2(r.r0, w5[0]);
    acc += mac2(__byte_perm(r.r0, r.r1, 0x5432), w5[1]);
    acc += mac2(r.r1, w5[2]);
    acc += mac2(__byte_perm(r.r1, r.r2, 0x5432), w5[3]);
    acc += mac2(r.r2, w5[4]);
}
__device__ __forceinline__ void row_mac(const Row3 r, const unsigned char* wp, unsigned& acc) {
    acc += mac2(r.r0, wp[0]);
    acc += mac2(__byte_perm(r.r0, r.r1, 0x5432), wp[1]);
    acc += mac2(r.r1, wp[2]);
    acc += mac2(__byte_perm(r.r1, r.r2, 0x5432), wp[3]);
    acc += mac2(r.r2, wp[4]);
}
// vec4 |max| scan helper
__device__ __forceinline__ float max4_scan(const float* src, int n4, int start, int stride) {
    const float4* s4 = (const float4*)src;
    float m = 0.0f;
    for (int i = start; i < n4; i += stride) {
        float4 v = s4[i];
        m = fmaxf(m, fmaxf(fmaxf(fabsf(v.x), fabsf(v.y)), fmaxf(fabsf(v.z), fabsf(v.w))));
    }
    return m;
}

// ---------------- k_maxA: maxima of x,w1,w2,w3 + reset activation slots -----
__global__ void k_maxA(const float* __restrict__ x,  const float* __restrict__ w1,
                       const float* __restrict__ w2, const float* __restrict__ w3) {
    pdl_trigger();                               // let conv1 launch + prefetch early
    int idx = blockIdx.y, bx = blockIdx.x;
    const float* src; int n4;
    switch (idx) {
        case 0: src = x;  n4 = NB*784/4; break;
        case 1: src = w1; n4 = 16*25/4;  break;
        case 2: src = w2; n4 = 32*400/4; break;
        default:src = w3; n4 = 64*800/4; break;
    }
    float m = max4_scan(src, n4, bx*blockDim.x + threadIdx.x, gridDim.x*blockDim.x);
    __shared__ int sm;
    if (threadIdx.x == 0) sm = 0;
    __syncthreads();
    atomicMax(&sm, __float_as_int(m));
    __syncthreads();
    if (threadIdx.x == 0) {
        g_pmax[idx*32 + bx] = __int_as_float(sm);
        if (idx == 0 && bx == 0) {
            g_maxbits[6] = 0; g_maxbits[7] = 0; g_maxbits[8] = 0; g_maxbits[9] = 0;
        }
    }
}

// ---------------- k_maxFW: maxima of fw1, fw2 (side stream) ----------------
__global__ void k_maxFW(const float* __restrict__ fw1, const float* __restrict__ fw2) {
    int idx = blockIdx.y, bx = blockIdx.x;
    const float* src; int n4; int slot;
    if (idx == 0) { src = fw1; n4 = 256*1024/4; slot = 4; }
    else          { src = fw2; n4 = 10*256/4;   slot = 5; }
    float m = max4_scan(src, n4, bx*blockDim.x + threadIdx.x, gridDim.x*blockDim.x);
    __shared__ int sm;
    if (threadIdx.x == 0) sm = 0;
    __syncthreads();
    atomicMax(&sm, __float_as_int(m));
    __syncthreads();
    if (threadIdx.x == 0) g_pmax[slot*32 + bx] = __int_as_float(sm);
}

// ---------------- k_qfw: quantize fw1 (spread) + fw2 (side stream) ---------
__global__ void k_qfw(const float* __restrict__ fw1, const float* __restrict__ fw2) {
    __shared__ float sc[2];
    int t = threadIdx.x;                        // 256
    if (t < 32) warp_scale_pmax(4, &sc[0]);
    else if (t < 64) warp_scale_pmax(5, &sc[1]);
    __syncthreads();
    float sfw1 = sc[0], sfw2 = sc[1];
    int base = blockIdx.x * 2048;               // 64 blocks * 2048 = 131072 uints
    for (int i = t; i < 2048; i += 256) {
        int gi = base + i, op = gi >> 10, k = gi & 1023;
        unsigned lo = quant1(fw1[(2*op)*1024 + k], sfw1);
        unsigned hi = quant1(fw1[(2*op+1)*1024 + k], sfw1);
        g_qfw1s[gi] = lo | (hi << 16);
    }
    if (blockIdx.x < 10)
        g_qfw2[blockIdx.x*256 + t] = quant1(fw2[blockIdx.x*256 + t], sfw2);
}

// ---------------- conv1 + quantize w2/w3 slices (PDL) ----------------
// grid 128 = (b, og4 of 4 o), block 784
__global__ void k_conv1(const float* __restrict__ x, const float* __restrict__ w1,
                        const float* __restrict__ b1, const float* __restrict__ w2,
                        const float* __restrict__ w3) {
    pdl_trigger();
    int blk = blockIdx.x; int b = blk >> 2, o0 = (blk & 3)*4;
    __shared__ unsigned short sa16[32*32];
    __shared__ unsigned char sw[4*32];
    __shared__ float sc[4];                     // sx, sw1, sw2, sw3
    __shared__ int smax;
    int t = threadIdx.x;                        // 784

    // --- independent prologue: prefetch floats, zero smem ---
    float xv = x[b*784 + t];                    // one pixel per thread, exact
    float w1v = (t < 100) ? w1[o0*25 + t]    : 0.0f;
    float w2v = (t < 100) ? w2[blk*100 + t]  : 0.0f;   // 128*100 = 12800
    float w3v = (t < 400) ? w3[blk*400 + t]  : 0.0f;   // 128*400 = 51200
    if (t == 0) smax = 0;
    if (t < 512) ((unsigned*)sa16)[t] = 0u;

    pdl_wait();                                 // k_maxA fully visible after this

    if (t < 32) warp_scale_pmax(0, &sc[0]);
    else if (t < 64)  warp_scale_pmax(1, &sc[1]);
    else if (t < 96)  warp_scale_pmax(2, &sc[2]);
    else if (t < 128) warp_scale_pmax(3, &sc[3]);
    __syncthreads();

    float sx = sc[0], sw1s = sc[1], sw2s = sc[2], sw3s = sc[3];
    {
        int r0 = t / 28, c0 = t - r0*28;
        sa16[(r0+2)*32 + (c0+2)] = quant1(xv, sx);
    }
    if (t < 100) {
        int ol = t / 25, k = t - ol*25;
        sw[ol*32 + k] = quant1(w1v, sw1s);
        g_qw2[blk*100 + t] = quant1(w2v, sw2s);
    }
    if (t < 400) g_qw3[blk*400 + t] = quant1(w3v, sw3s);
    __syncthreads();

    int o_l = t / 196, pos = t - o_l*196;
    int py = pos / 14, px = pos - py*14;
    const unsigned char* wb = sw + o_l*32;

    unsigned acc0 = 0, acc1 = 0;
    Row3 cur = load_row3(&sa16[(2*py)*32 + 2*px]);
    #pragma unroll
    for (int ky = 0; ky < 5; ky++) {
        Row3 nxt = load_row3(&sa16[(2*py + ky + 1)*32 + 2*px]);
        row_mac(cur, wb + ky*5, acc0);
        row_mac(nxt, wb + ky*5, acc1);
        cur = nxt;
    }
    int best = max(max((int)(acc0 & 0xFFFF), (int)(acc0 >> 16)),
                   max((int)(acc1 & 0xFFFF), (int)(acc1 >> 16)));
    int o = o0 + o_l;
    float v = fmaxf((float)best + b1[o], 0.0f);
    g_act1[(b*16 + o)*196 + pos] = v;
    atomicMax(&smax, __float_as_int(v));
    __syncthreads();
    if (t == 0) atomicMax(&g_maxbits[6], smax);
}

// ---------------- conv2 (PDL, vec4 loads): act1 -> relu+pool -> act2 -------
// grid 256 = (b, og8 of 4 o), block 448 = o_l(4)x112 + ys(2)x56 + kc(8,2ch)x7 + xq(7)
__global__ void k_conv2(const float* __restrict__ b2) {
    pdl_trigger();
    int blk = blockIdx.x; int b = blk >> 3, o0 = (blk & 7)*4;
    __shared__ unsigned short sa16[16*18*20];   // ch stride 360 el, row 20 el
    __shared__ unsigned char swq[4*400];
    __shared__ int psum[8*4*14*14];             // [kc][o_l][y][x]
    __shared__ float sc1;
    __shared__ int smax;
    int t = threadIdx.x;                        // 448

    if (t == 0) smax = 0;
    for (int i = t; i < 2880; i += 448) ((unsigned*)sa16)[i] = 0u;

    pdl_wait();                                 // conv1's act1/qw2/maxbits visible

    if (t == 0) sc1 = scale_from_bits(6);
    __syncthreads();

    float sa1 = sc1;
    {
        const float4* src = (const float4*)(g_act1 + b*3136);
        for (int j = t; j < 784; j += 448) {    // 784 float4 = 3136 floats
            float4 v = src[j];
            int i0 = j*4;
            #pragma unroll
            for (int e = 0; e < 4; e++) {
                int ii = i0 + e;
                int ch = ii / 196, rem = ii - ch*196;
                int r = rem / 14, c = rem - r*14;
                float fv = (e == 0) ? v.x : (e == 1) ? v.y : (e == 2) ? v.z : v.w;
                sa16[ch*360 + (r+2)*20 + (c+2)] = quant1(fv, sa1);
            }
        }
    }
    if (t < 100) ((uint4*)swq)[t] = ((const uint4*)(g_qw2 + o0*400))[t];
    __syncthreads();

    {
        int o_l = t / 112, r = t - o_l*112;
        int ys = r / 56, r2 = r - ys*56;
        int kc = r2 / 7, xq = r2 - kc*7;
        int rbase = ys*7;                       // rows rbase..rbase+10, y rbase..rbase+6

        unsigned acc[7];
        #pragma unroll
        for (int j = 0; j < 7; j++) acc[j] = 0;

        #pragma unroll
        for (int cc = 0; cc < 2; cc++) {
            int ch = kc*2 + cc;
            const unsigned short* base = sa16 + ch*360 + xq*2;
            const unsigned char* wp = swq + o_l*400 + ch*25;
            unsigned w[25];
            #pragma unroll
            for (int i = 0; i < 25; i++) w[i] = wp[i];
            #pragma unroll
            for (int rr = 0; rr < 11; rr++) {
                Row3 row = load_row3(base + (rbase + rr)*20);
                #pragma unroll
                for (int ky = 0; ky < 5; ky++) {
                    int yr = rr - ky;
                    if (yr >= 0 && yr < 7) row_mac_r(row, w + ky*5, acc[yr]);
                }
            }
        }
        int pbase = ((kc*4 + o_l)*14 + rbase)*14 + xq*2;
        #pragma unroll
        for (int j = 0; j < 7; j++) {
            psum[pbase + j*14]     = acc[j] & 0xFFFF;
            psum[pbase + j*14 + 1] = acc[j] >> 16;
        }
    }
    __syncthreads();

    if (t < 196) {
        int o_r = t / 49, p = t - o_r*49;
        int py = p / 7, px = p - py*7;
        int best = INT_MIN_V;
        #pragma unroll
        for (int dy = 0; dy < 2; dy++) {
            #pragma unroll
            for (int dx = 0; dx < 2; dx++) {
                int yy = 2*py + dy, xx = 2*px + dx;
                int s = 0;
                #pragma unroll
                for (int k = 0; k < 8; k++)
                    s += psum[((k*4 + o_r)*14 + yy)*14 + xx];
                best = max(best, s);
            }
        }
        int o = o0 + o_r;
        float v = fmaxf((float)best + b2[o], 0.0f);
        g_act2[(b*32 + o)*49 + p] = v;
        atomicMax(&smax, __float_as_int(v));
    }
    __syncthreads();
    if (t == 0) atomicMax(&g_maxbits[7], smax);
}

// ---------------- conv3 (PDL, vec4 loads): act2 -> relu+pool(pad=1) -> act3
// grid 512 = (b, og16 of 4 o), block 512: t = o_l(4)*128 + ys(2)*64 + kc(16,2ch)*4 + xq(4)
__global__ void k_conv3(const float* __restrict__ b3) {
    pdl_trigger();
    int blk = blockIdx.x; int b = blk >> 4, o0 = (blk & 15)*4;
    __shared__ unsigned short sa16[32*11*12];   // ch stride 132 el, row 12 el
    __shared__ unsigned char swq[4*800];
    __shared__ int psum[16*4*56];               // [kc][o_l][y*8+x]
    __shared__ int stot[4*56];
    __shared__ float sc1;
    __shared__ int smax;
    int t = threadIdx.x;                        // 512

    if (t == 0) smax = 0;
    for (int i = t; i < 2112; i += 512) ((unsigned*)sa16)[i] = 0u;

    pdl_wait();                                 // conv2's act2/maxbits visible

    if (t == 0) sc1 = scale_from_bits(7);
    __syncthreads();

    float sa2 = sc1;
    if (t < 392) {                              // 392 float4 = 1568 floats
        float4 v = ((const float4*)(g_act2 + b*1568))[t];
        int i0 = t*4;
        #pragma unroll
        for (int e = 0; e < 4; e++) {
            int ii = i0 + e;
            int ch = ii / 49, rem = ii - ch*49;
            int r = rem / 7, c = rem - r*7;
            float fv = (e == 0) ? v.x : (e == 1) ? v.y : (e == 2) ? v.z : v.w;
            sa16[ch*132 + (r+2)*12 + (c+2)] = quant1(fv, sa2);
        }
    }
    if (t < 200) ((uint4*)swq)[t] = ((const uint4*)(g_qw3 + o0*800))[t];
    __syncthreads();

    {
        int o_l = t >> 7, r7 = t & 127;
        int ys = r7 >> 6, kc = (r7 >> 2) & 15, xq = r7 & 3;
        int rbase = ys*3;                       // rows rbase..rbase+7; y rbase..rbase+3
        unsigned acc[4];
        #pragma unroll
        for (int j = 0; j < 4; j++) acc[j] = 0;

        #pragma unroll
        for (int cc = 0; cc < 2; cc++) {
            int ch = kc*2 + cc;
            const unsigned short* base = sa16 + ch*132 + xq*2;
            const unsigned char* wp = swq + o_l*800 + ch*25;
            unsigned w[25];
            #pragma unroll
            for (int i = 0; i < 25; i++) w[i] = wp[i];
            #pragma unroll
            for (int rr = 0; rr < 8; rr++) {
                Row3 row = load_row3(base + (rbase + rr)*12);
                #pragma unroll
                for (int ky = 0; ky < 5; ky++) {
                    int yr = rr - ky;
                    if (yr >= 0 && yr < 4) row_mac_r(row, w + ky*5, acc[yr]);
                }
            }
        }
        int pbase = (kc*4 + o_l)*56 + rbase*8 + xq*2;
        #pragma unroll
        for (int j = 0; j < 4; j++) {
            if (j >= ys) {                      // ys=1 skips duplicate y=3
                psum[pbase + j*8]     = acc[j] & 0xFFFF;
                psum[pbase + j*8 + 1] = acc[j] >> 16;   // x=7 garbage, never pooled
            }
        }
    }
    __syncthreads();

    if (t < 224) {                              // kc-sum
        int o_r = t / 56, p = t - o_r*56;
        int s = 0;
        #pragma unroll
        for (int k = 0; k < 16; k++) s += psum[(k*4 + o_r)*56 + p];
        stot[o_r*56 + p] = s;
    }
    __syncthreads();

    if (t < 64) {
        int o_r = t >> 4, idx2 = t & 15;
        int py = idx2 >> 2, px = idx2 & 3;
        int best = INT_MIN_V;
        #pragma unroll
        for (int dy = 0; dy < 2; dy++) {
            int ry = 2*py - 1 + dy;
            if ((unsigned)ry >= 7u) continue;
            #pragma unroll
            for (int dx = 0; dx < 2; dx++) {
                int rx = 2*px - 1 + dx;
                if ((unsigned)rx >= 7u) continue;
                best = max(best, stot[o_r*56 + ry*8 + rx]);
            }
        }
        int o = o0 + o_r;
        float v = fmaxf((float)best + b3[o], 0.0f);
        g_act3[b*1024 + o*16 + idx2] = v;
        atomicMax(&smax, __float_as_int(v));
    }
    __syncthreads();
    if (t == 0) atomicMax(&g_maxbits[8], smax);
}

// ---------------- fc1 (PDL, vec4): spread-weight dual-output dot ------------
// grid 256 = (b, og8 of 16 o-pairs), block 256 = op_l(16) x ks(16, 64 k each)
__global__ void k_fc1(const float* __restrict__ fb1) {
    pdl_trigger();
    int blk = blockIdx.x; int b = blk >> 3, og = blk & 7;
    __shared__ unsigned char qa[1024];
    __shared__ int red[512];
    __shared__ float sc1;
    __shared__ int smax;
    int t = threadIdx.x;                        // 256

    if (t == 0) smax = 0;
    pdl_wait();                                 // conv3's act3/maxbits visible
    if (t == 0) sc1 = scale_from_bits(8);
    __syncthreads();
    float sa3 = sc1;
    {
        float4 v = ((const float4*)(g_act3 + b*1024))[t];   // 256 float4 = 1024
        uchar4 q;
        q.x = quant1(v.x, sa3); q.y = quant1(v.y, sa3);
        q.z = quant1(v.z, sa3); q.w = quant1(v.w, sa3);
        ((uchar4*)qa)[t] = q;
    }
    __syncthreads();

    int op_l = t >> 4, ks = t & 15;
    int op = og*16 + op_l;
    const uint4* wp = (const uint4*)(g_qfw1s + op*1024 + ks*64);
    const unsigned* ap = (const unsigned*)(qa + ks*64);
    unsigned acc = 0;
    #pragma unroll
    for (int i = 0; i < 16; i++) {
        uint4 w = wp[i];
        unsigned au = ap[i];
        acc += __byte_perm(w.x * __byte_perm(au, 0u, 0x4440), 0u, 0x4341);
        acc += __byte_perm(w.y * __byte_perm(au, 0u, 0x4441), 0u, 0x4341);
        acc += __byte_perm(w.z * __byte_perm(au, 0u, 0x4442), 0u, 0x4341);
        acc += __byte_perm(w.w * __byte_perm(au, 0u, 0x4443), 0u, 0x4341);
    }
    red[op_l*16 + ks]       = acc & 0xFFFF;
    red[256 + op_l*16 + ks] = acc >> 16;
    __syncthreads();

    if (t < 32) {
        int op_r = t >> 1, parity = t & 1;
        int base = parity*256 + op_r*16;
        int s = 0;
        #pragma unroll
        for (int i = 0; i < 16; i++) s += red[base + i];
        int o = og*32 + op_r*2 + parity;
        float v = fmaxf((float)s + fb1[o], 0.0f);
        g_fc1[b*256 + o] = v;
        atomicMax(&smax, __float_as_int(v));
    }
    __syncthreads();
    if (t == 0) atomicMax(&g_maxbits[9], smax);
}

// ---------------- fc2 + log_softmax (PDL). grid 32, block 128 --------------
__global__ void k_fc2(const float* __restrict__ fb2, float* __restrict__ out) {
    int b = blockIdx.x;
    __shared__ unsigned char qa[256];
    __shared__ int red[80];
    __shared__ float vals[10];
    __shared__ float mred[2];
    __shared__ float sc1;
    int t = threadIdx.x;                        // 128

    pdl_wait();                                 // fc1's g_fc1/maxbits visible
    if (t == 0) sc1 = scale_from_bits(9);
    __syncthreads();
    float sf1 = sc1;
    for (int i = t; i < 256; i += 128) qa[i] = quant1(g_fc1[b*256 + i], sf1);
    __syncthreads();

    if (t < 80) {
        int o = t >> 3, ks = t & 7;
        const unsigned char* wp = g_qfw2 + o*256 + ks*32;
        const unsigned char* ap = qa + ks*32;
        int s = 0;
        #pragma unroll
        for (int k = 0; k < 32; k++) s += (ap[k] * wp[k]) >> 8;
        red[t] = s;
    }
    __syncthreads();
    if (t < 10) {
        int s = 0;
        #pragma unroll
        for (int i = 0; i < 8; i++) s += red[t*8 + i];
        vals[t] = (float)s + fb2[t];
    }
    __syncthreads();
    if (t == 0) {
        float m = vals[0];
        #pragma unroll
        for (int i = 1; i < 10; i++) m = fmaxf(m, vals[i]);
        float se = 0.0f;
        #pragma unroll
        for (int i = 0; i < 10; i++) se += expf(vals[i] - m);
        mred[0] = m; mred[1] = logf(se);
    }
    __syncthreads();
    if (t < 10) out[b*10 + t] = vals[t] - mred[0] - mred[1];
}

// ---------------- launch ----------------
static inline void launch_pdl(void* fn, dim3 grid, dim3 block, void** args) {
    cudaLaunchAttribute attr[1];
    attr[0].id = cudaLaunchAttributeProgrammaticStreamSerialization;
    attr[0].val.programmaticStreamSerializationAllowed = 1;
    cudaLaunchConfig_t cfg = {};
    cfg.gridDim = grid; cfg.blockDim = block;
    cfg.dynamicSmemBytes = 0; cfg.stream = 0;
    cfg.attrs = attr; cfg.numAttrs = 1;
    cudaLaunchKernelExC(&cfg, fn, args);
}

extern "C" void kernel_launch(void* const* d_in, const int* in_sizes, int n_in,
                              void* d_out, int out_size) {
    const float* x   = (const float*)d_in[0];
    // d_in[1] = lut — unused: lut[a][b] == (a*b)>>8 exactly
    const float* w1  = (const float*)d_in[2];
    const float* b1  = (const float*)d_in[3];
    const float* w2  = (const float*)d_in[4];
    const float* b2  = (const float*)d_in[5];
    const float* w3  = (const float*)d_in[6];
    const float* b3  = (const float*)d_in[7];
    const float* fw1 = (const float*)d_in[8];
    const float* fb1 = (const float*)d_in[9];
    const float* fw2 = (const float*)d_in[10];
    const float* fb2 = (const float*)d_in[11];
    float* out = (float*)d_out;

    static cudaStream_t s_side = 0;
    static cudaEvent_t ev_fork = 0, ev_join = 0;
    if (s_side == 0) {
        cudaStreamCreateWithFlags(&s_side, cudaStreamNonBlocking);
        cudaEventCreateWithFlags(&ev_fork, cudaEventDisableTiming);
        cudaEventCreateWithFlags(&ev_join, cudaEventDisableTiming);
    }

    // side branch: fw1/fw2 quant path (needed only by fc1/fc2)
    cudaEventRecord(ev_fork, 0);
    cudaStreamWaitEvent(s_side, ev_fork, 0);
    k_maxFW<<<dim3(32, 2), 256, 0, s_side>>>(fw1, fw2);
    k_qfw  <<<64, 256, 0, s_side>>>(fw1, fw2);
    cudaEventRecord(ev_join, s_side);

    // main chain with PDL at every boundary
    k_maxA <<<dim3(32, 4), 256>>>(x, w1, w2, w3);
    {
        void* a[] = { (void*)&x, (void*)&w1, (void*)&b1, (void*)&w2, (void*)&w3 };
        launch_pdl((void*)k_conv1, dim3(128), dim3(784), a);
    }
    {
        void* a[] = { (void*)&b2 };
        launch_pdl((void*)k_conv2, dim3(256), dim3(448), a);
    }
    {
        void* a[] = { (void*)&b3 };
        launch_pdl((void*)k_conv3, dim3(512), dim3(512), a);
    }
    cudaStreamWaitEvent(0, ev_join, 0);         // join before fc needs g_qfw1s/g_qfw2
    {
        void* a[] = { (void*)&fb1 };
        launch_pdl((void*)k_fc1, dim3(256), dim3(256), a);
    }
    {
        void* a[] = { (void*)&fb2, (void*)&out };
        launch_pdl((void*)k_fc2, dim3(32), dim3(128), a);
    }
}